// round 1
// baseline (speedup 1.0000x reference)
#include <cuda_runtime.h>
#include <cuda_bf16.h>
#include <math.h>

// Problem constants (fixed by reference)
constexpr int NN  = 100000;
constexpr int EE  = 1600000;
constexpr int FIN = 512;
constexpr int HH  = 128;
constexpr int CC  = 64;

// Scratch (device globals: allocation-free rule)
__device__ float g_h[(size_t)NN * HH];     // GEMM output / transformed features
__device__ float g_acc[(size_t)NN * HH];   // scatter accumulator / logits
__device__ float g_y[(size_t)NN * HH];     // layer output
__device__ float g_dinv[NN];               // deg accumulator -> deg^-1/2
__device__ float g_norm[EE];               // per-edge norm

// ---------------------------------------------------------------------------
// Tiled SGEMM: C[M x Nout] = A[M x K] @ B[K x Nout] + bias, optional relu.
// BM=128, BN=64, BK=16, TM=8, TN=4, 256 threads.
// ---------------------------------------------------------------------------
#define BM 128
#define BN 64
#define BK 16
#define TM 8
#define TN 4

__global__ __launch_bounds__(256) void sgemm_bias(
    const float* __restrict__ A, const float* __restrict__ B,
    const float* __restrict__ bias, float* __restrict__ C,
    int M, int K, int Nout, int relu)
{
    __shared__ __align__(16) float As[BK][BM + 4];
    __shared__ __align__(16) float Bs[BK][BN];

    const int tid  = threadIdx.x;
    const int tcol = tid & 15;   // 0..15 -> 4-col group
    const int trow = tid >> 4;   // 0..15 -> 8-row group
    const int blockRow = blockIdx.x * BM;
    const int blockCol = blockIdx.y * BN;

    float acc[TM][TN];
#pragma unroll
    for (int i = 0; i < TM; i++)
#pragma unroll
        for (int j = 0; j < TN; j++) acc[i][j] = 0.f;

    // A-load mapping: 128 rows x 4 float4/row = 512 float4; 2 per thread.
    const int a_row = tid & 127;    // row within tile
    const int a_kq0 = tid >> 7;     // 0/1, second pass +2
    // B-load mapping: 16 rows x 16 float4 = 256 float4; 1 per thread.
    const int b_row = tid >> 4;
    const int b_cq  = tid & 15;

    for (int k0 = 0; k0 < K; k0 += BK) {
        // Load A tile (transposed into smem)
#pragma unroll
        for (int p = 0; p < 2; p++) {
            int kq = a_kq0 + p * 2;  // 0..3
            int grow = blockRow + a_row;
            float4 v = make_float4(0.f, 0.f, 0.f, 0.f);
            if (grow < M)
                v = *(const float4*)(A + (size_t)grow * K + k0 + kq * 4);
            As[kq * 4 + 0][a_row] = v.x;
            As[kq * 4 + 1][a_row] = v.y;
            As[kq * 4 + 2][a_row] = v.z;
            As[kq * 4 + 3][a_row] = v.w;
        }
        // Load B tile
        {
            float4 v = *(const float4*)(B + (size_t)(k0 + b_row) * Nout +
                                        blockCol + b_cq * 4);
            *(float4*)&Bs[b_row][b_cq * 4] = v;
        }
        __syncthreads();

#pragma unroll
        for (int kk = 0; kk < BK; kk++) {
            const float4* ap = (const float4*)&As[kk][trow * TM];
            float4 a0 = ap[0], a1 = ap[1];
            float4 b  = *(const float4*)&Bs[kk][tcol * TN];
            float a[TM] = {a0.x, a0.y, a0.z, a0.w, a1.x, a1.y, a1.z, a1.w};
            float bb[TN] = {b.x, b.y, b.z, b.w};
#pragma unroll
            for (int i = 0; i < TM; i++)
#pragma unroll
                for (int j = 0; j < TN; j++)
                    acc[i][j] = fmaf(a[i], bb[j], acc[i][j]);
        }
        __syncthreads();
    }

    // Epilogue
#pragma unroll
    for (int i = 0; i < TM; i++) {
        int grow = blockRow + trow * TM + i;
        if (grow >= M) continue;
#pragma unroll
        for (int j = 0; j < TN; j++) {
            int gcol = blockCol + tcol * TN + j;
            float v = acc[i][j] + bias[gcol];
            if (relu) v = fmaxf(v, 0.f);
            C[(size_t)grow * Nout + gcol] = v;
        }
    }
}

// ---------------------------------------------------------------------------
// Graph preprocessing
// ---------------------------------------------------------------------------
__global__ void count_deg(const int* __restrict__ dst, float* __restrict__ deg, int E)
{
    int e = blockIdx.x * blockDim.x + threadIdx.x;
    if (e < E) atomicAdd(&deg[dst[e]], 1.0f);
}

__global__ void fin_deg(float* __restrict__ dinv, int n)
{
    int i = blockIdx.x * blockDim.x + threadIdx.x;
    if (i < n) dinv[i] = rsqrtf(dinv[i] + 1.0f);  // +1 for self-loop
}

__global__ void comp_norm(const int* __restrict__ src, const int* __restrict__ dst,
                          const float* __restrict__ dinv, float* __restrict__ norm, int E)
{
    int e = blockIdx.x * blockDim.x + threadIdx.x;
    if (e < E) norm[e] = dinv[src[e]] * dinv[dst[e]];
}

// ---------------------------------------------------------------------------
// Edge scatter: acc[dst] += h[src] * norm.  32 threads per edge, float4 lanes.
// ---------------------------------------------------------------------------
__global__ __launch_bounds__(256) void scatter_edges(
    const float* __restrict__ h, const int* __restrict__ src,
    const int* __restrict__ dst, const float* __restrict__ norm,
    float* __restrict__ acc, int E)
{
    int t = blockIdx.x * blockDim.x + threadIdx.x;
    int e = t >> 5;
    if (e >= E) return;
    int lane = t & 31;
    int s = src[e];
    int d = dst[e];
    float nrm = norm[e];
    float4 v = *(const float4*)(h + (size_t)s * HH + lane * 4);
    float* o = acc + (size_t)d * HH + lane * 4;
    atomicAdd(o + 0, v.x * nrm);
    atomicAdd(o + 1, v.y * nrm);
    atomicAdd(o + 2, v.z * nrm);
    atomicAdd(o + 3, v.w * nrm);
}

// Self-loop contribution + relu: y = relu(acc + h * dinv^2)
__global__ void finalize_conv(const float* __restrict__ acc, const float* __restrict__ h,
                              const float* __restrict__ dinv, float* __restrict__ y, int n)
{
    int i = blockIdx.x * blockDim.x + threadIdx.x;
    if (i >= n) return;
    int node = i >> 7;  // /HH
    float di = dinv[node];
    y[i] = fmaxf(acc[i] + h[i] * di * di, 0.f);
}

// ---------------------------------------------------------------------------
// log_softmax over C=64 classes; 1 warp per row, 2 classes per lane.
// ---------------------------------------------------------------------------
__global__ void log_softmax_k(const float* __restrict__ logits, float* __restrict__ out, int N)
{
    int row = blockIdx.x * blockDim.y + threadIdx.y;
    if (row >= N) return;
    int lane = threadIdx.x;
    const float* lr = logits + (size_t)row * CC;
    float v0 = lr[lane], v1 = lr[lane + 32];
    float m = fmaxf(v0, v1);
#pragma unroll
    for (int o = 16; o; o >>= 1) m = fmaxf(m, __shfl_xor_sync(0xffffffffu, m, o));
    float s = expf(v0 - m) + expf(v1 - m);
#pragma unroll
    for (int o = 16; o; o >>= 1) s += __shfl_xor_sync(0xffffffffu, s, o);
    float ls = m + logf(s);
    float* orow = out + (size_t)row * CC;
    orow[lane] = v0 - ls;
    orow[lane + 32] = v1 - ls;
}

// ---------------------------------------------------------------------------
// Launch
// ---------------------------------------------------------------------------
extern "C" void kernel_launch(void* const* d_in, const int* in_sizes, int n_in,
                              void* d_out, int out_size)
{
    const float* x     = (const float*)d_in[0];
    const int*   ei    = (const int*)d_in[1];
    const float* W0    = (const float*)d_in[2];
    const float* b0    = (const float*)d_in[3];
    const float* W1    = (const float*)d_in[4];
    const float* b1    = (const float*)d_in[5];
    const float* W2    = (const float*)d_in[6];
    const float* b2    = (const float*)d_in[7];
    const float* fc1_w = (const float*)d_in[8];
    const float* fc1_b = (const float*)d_in[9];
    const float* fc2_w = (const float*)d_in[10];
    const float* fc2_b = (const float*)d_in[11];
    const float* fc3_w = (const float*)d_in[12];
    const float* fc3_b = (const float*)d_in[13];

    const int N = in_sizes[0] / FIN;   // 100000
    const int E = in_sizes[1] / 2;     // 1600000
    const int* src = ei;
    const int* dst = ei + E;

    float *h_, *acc_, *y_, *dinv_, *norm_;
    cudaGetSymbolAddress((void**)&h_,    g_h);
    cudaGetSymbolAddress((void**)&acc_,  g_acc);
    cudaGetSymbolAddress((void**)&y_,    g_y);
    cudaGetSymbolAddress((void**)&dinv_, g_dinv);
    cudaGetSymbolAddress((void**)&norm_, g_norm);

    const int T = 256;
    dim3 gemm_grid((N + BM - 1) / BM, HH / BN);     // 782 x 2
    dim3 gemm_grid_c((N + BM - 1) / BM, CC / BN);   // 782 x 1

    // ---- graph normalization ----
    cudaMemsetAsync(dinv_, 0, (size_t)N * sizeof(float));
    count_deg<<<(E + T - 1) / T, T>>>(dst, dinv_, E);
    fin_deg<<<(N + T - 1) / T, T>>>(dinv_, N);
    comp_norm<<<(E + T - 1) / T, T>>>(src, dst, dinv_, norm_, E);

    const int scatter_blocks = (int)(((size_t)E * 32 + T - 1) / T);
    const int nh = N * HH;

    // ---- conv0: x[N,512] @ W0 -> scatter -> relu -> y_ ----
    sgemm_bias<<<gemm_grid, T>>>(x, W0, b0, h_, N, FIN, HH, 0);
    cudaMemsetAsync(acc_, 0, (size_t)nh * sizeof(float));
    scatter_edges<<<scatter_blocks, T>>>(h_, src, dst, norm_, acc_, E);
    finalize_conv<<<(nh + T - 1) / T, T>>>(acc_, h_, dinv_, y_, nh);

    // ---- conv1 ----
    sgemm_bias<<<gemm_grid, T>>>(y_, W1, b1, h_, N, HH, HH, 0);
    cudaMemsetAsync(acc_, 0, (size_t)nh * sizeof(float));
    scatter_edges<<<scatter_blocks, T>>>(h_, src, dst, norm_, acc_, E);
    finalize_conv<<<(nh + T - 1) / T, T>>>(acc_, h_, dinv_, y_, nh);

    // ---- conv2 ----
    sgemm_bias<<<gemm_grid, T>>>(y_, W2, b2, h_, N, HH, HH, 0);
    cudaMemsetAsync(acc_, 0, (size_t)nh * sizeof(float));
    scatter_edges<<<scatter_blocks, T>>>(h_, src, dst, norm_, acc_, E);
    finalize_conv<<<(nh + T - 1) / T, T>>>(acc_, h_, dinv_, y_, nh);

    // ---- MLP ----
    sgemm_bias<<<gemm_grid, T>>>(y_, fc1_w, fc1_b, h_, N, HH, HH, 1);
    sgemm_bias<<<gemm_grid, T>>>(h_, fc2_w, fc2_b, y_, N, HH, HH, 1);
    sgemm_bias<<<gemm_grid_c, T>>>(y_, fc3_w, fc3_b, acc_, N, HH, CC, 0);

    // ---- log_softmax ----
    dim3 ls_block(32, 8);
    log_softmax_k<<<(N + 7) / 8, ls_block>>>(acc_, (float*)d_out, N);
}

// round 3
// speedup vs baseline: 2.9046x; 2.9046x over previous
#include <cuda_runtime.h>
#include <cuda_bf16.h>
#include <math.h>

// Problem constants (fixed by reference)
constexpr int NN  = 100000;
constexpr int EE  = 1600000;
constexpr int FIN = 512;
constexpr int HH  = 128;
constexpr int CC  = 64;

// Scratch (device globals: allocation-free rule)
__device__ float g_h[(size_t)NN * HH];     // GEMM output / transformed features
__device__ float g_acc[(size_t)NN * HH];   // scatter accumulator / logits
__device__ float g_y[(size_t)NN * HH];     // layer output
__device__ float g_dinv[NN];               // deg accumulator -> deg^-1/2
__device__ float g_norm[EE];               // per-edge norm

// ---------------------------------------------------------------------------
// Tiled SGEMM, double-buffered: C = A[MxK] @ B[KxNout] + bias, optional relu.
// BM=128, BN=64, BK=16, TM=8, TN=4, 256 threads.
// ---------------------------------------------------------------------------
#define BM 128
#define BN 64
#define BK 16
#define TM 8
#define TN 4

__global__ __launch_bounds__(256) void sgemm_bias(
    const float* __restrict__ A, const float* __restrict__ B,
    const float* __restrict__ bias, float* __restrict__ C,
    int M, int K, int Nout, int relu)
{
    __shared__ __align__(16) float As[2][BK][BM + 4];
    __shared__ __align__(16) float Bs[2][BK][BN];

    const int tid  = threadIdx.x;
    const int tcol = tid & 15;   // 0..15 -> 4-col group
    const int trow = tid >> 4;   // 0..15 -> 8-row group
    const int blockRow = blockIdx.x * BM;
    const int blockCol = blockIdx.y * BN;

    float acc[TM][TN];
#pragma unroll
    for (int i = 0; i < TM; i++)
#pragma unroll
        for (int j = 0; j < TN; j++) acc[i][j] = 0.f;

    // A-load mapping: 128 rows x 4 float4/row = 512 float4; 2 per thread.
    const int a_row = tid & 127;
    const int a_kq0 = tid >> 7;     // 0/1; passes at kq0 and kq0+2
    const int a_grow = blockRow + a_row;
    const bool a_ok = (a_grow < M);
    // B-load mapping: 16 rows x 16 float4 = 256 float4; 1 per thread.
    const int b_row = tid >> 4;
    const int b_cq  = tid & 15;

    float4 a_reg[2], b_reg;

    // --- prologue: load tile 0 into regs, store to smem[0] ---
#pragma unroll
    for (int p = 0; p < 2; p++) {
        int kq = a_kq0 + p * 2;
        a_reg[p] = a_ok ? *(const float4*)(A + (size_t)a_grow * K + kq * 4)
                        : make_float4(0.f, 0.f, 0.f, 0.f);
    }
    b_reg = *(const float4*)(B + (size_t)b_row * Nout + blockCol + b_cq * 4);

#pragma unroll
    for (int p = 0; p < 2; p++) {
        int kq = a_kq0 + p * 2;
        As[0][kq * 4 + 0][a_row] = a_reg[p].x;
        As[0][kq * 4 + 1][a_row] = a_reg[p].y;
        As[0][kq * 4 + 2][a_row] = a_reg[p].z;
        As[0][kq * 4 + 3][a_row] = a_reg[p].w;
    }
    *(float4*)&Bs[0][b_row][b_cq * 4] = b_reg;
    __syncthreads();

    int buf = 0;
    for (int k0 = BK; k0 < K; k0 += BK) {
        // prefetch next tile into registers
#pragma unroll
        for (int p = 0; p < 2; p++) {
            int kq = a_kq0 + p * 2;
            a_reg[p] = a_ok ? *(const float4*)(A + (size_t)a_grow * K + k0 + kq * 4)
                            : make_float4(0.f, 0.f, 0.f, 0.f);
        }
        b_reg = *(const float4*)(B + (size_t)(k0 + b_row) * Nout + blockCol + b_cq * 4);

        // compute on current buffer
#pragma unroll
        for (int kk = 0; kk < BK; kk++) {
            const float4* ap = (const float4*)&As[buf][kk][trow * TM];
            float4 a0 = ap[0], a1 = ap[1];
            float4 b  = *(const float4*)&Bs[buf][kk][tcol * TN];
            float a[TM] = {a0.x, a0.y, a0.z, a0.w, a1.x, a1.y, a1.z, a1.w};
            float bb[TN] = {b.x, b.y, b.z, b.w};
#pragma unroll
            for (int i = 0; i < TM; i++)
#pragma unroll
                for (int j = 0; j < TN; j++)
                    acc[i][j] = fmaf(a[i], bb[j], acc[i][j]);
        }

        // store prefetched regs into other buffer
#pragma unroll
        for (int p = 0; p < 2; p++) {
            int kq = a_kq0 + p * 2;
            As[buf ^ 1][kq * 4 + 0][a_row] = a_reg[p].x;
            As[buf ^ 1][kq * 4 + 1][a_row] = a_reg[p].y;
            As[buf ^ 1][kq * 4 + 2][a_row] = a_reg[p].z;
            As[buf ^ 1][kq * 4 + 3][a_row] = a_reg[p].w;
        }
        *(float4*)&Bs[buf ^ 1][b_row][b_cq * 4] = b_reg;
        __syncthreads();
        buf ^= 1;
    }

    // final tile compute
#pragma unroll
    for (int kk = 0; kk < BK; kk++) {
        const float4* ap = (const float4*)&As[buf][kk][trow * TM];
        float4 a0 = ap[0], a1 = ap[1];
        float4 b  = *(const float4*)&Bs[buf][kk][tcol * TN];
        float a[TM] = {a0.x, a0.y, a0.z, a0.w, a1.x, a1.y, a1.z, a1.w};
        float bb[TN] = {b.x, b.y, b.z, b.w};
#pragma unroll
        for (int i = 0; i < TM; i++)
#pragma unroll
            for (int j = 0; j < TN; j++)
                acc[i][j] = fmaf(a[i], bb[j], acc[i][j]);
    }

    // Epilogue
    float4 bv = *(const float4*)(bias + blockCol + tcol * TN);
#pragma unroll
    for (int i = 0; i < TM; i++) {
        int grow = blockRow + trow * TM + i;
        if (grow >= M) continue;
        float4 v;
        v.x = acc[i][0] + bv.x;
        v.y = acc[i][1] + bv.y;
        v.z = acc[i][2] + bv.z;
        v.w = acc[i][3] + bv.w;
        if (relu) {
            v.x = fmaxf(v.x, 0.f); v.y = fmaxf(v.y, 0.f);
            v.z = fmaxf(v.z, 0.f); v.w = fmaxf(v.w, 0.f);
        }
        *(float4*)(C + (size_t)grow * Nout + blockCol + tcol * TN) = v;
    }
}

// ---------------------------------------------------------------------------
// Graph preprocessing
// ---------------------------------------------------------------------------
__global__ void count_deg(const int* __restrict__ dst, float* __restrict__ deg, int E)
{
    int e = blockIdx.x * blockDim.x + threadIdx.x;
    if (e < E) atomicAdd(&deg[dst[e]], 1.0f);
}

__global__ void fin_deg(float* __restrict__ dinv, int n)
{
    int i = blockIdx.x * blockDim.x + threadIdx.x;
    if (i < n) dinv[i] = rsqrtf(dinv[i] + 1.0f);  // +1 for self-loop
}

__global__ void comp_norm(const int* __restrict__ src, const int* __restrict__ dst,
                          const float* __restrict__ dinv, float* __restrict__ norm, int E)
{
    int e = blockIdx.x * blockDim.x + threadIdx.x;
    if (e < E) norm[e] = dinv[src[e]] * dinv[dst[e]];
}

// ---------------------------------------------------------------------------
// Edge scatter: acc[dst] += h[src] * norm.  32 threads per edge;
// each lane handles 4 floats with one red.global.add.v4.f32.
// ---------------------------------------------------------------------------
__global__ __launch_bounds__(256) void scatter_edges(
    const float* __restrict__ h, const int* __restrict__ src,
    const int* __restrict__ dst, const float* __restrict__ norm,
    float* __restrict__ acc, int E)
{
    int t = blockIdx.x * blockDim.x + threadIdx.x;
    int e = t >> 5;
    if (e >= E) return;
    int lane = t & 31;
    int s = __ldg(src + e);
    int d = __ldg(dst + e);
    float nrm = __ldg(norm + e);
    float4 v = *(const float4*)(h + (size_t)s * HH + lane * 4);
    float* o = acc + (size_t)d * HH + lane * 4;
    asm volatile("red.global.add.v4.f32 [%0], {%1, %2, %3, %4};"
                 :: "l"(o), "f"(v.x * nrm), "f"(v.y * nrm),
                    "f"(v.z * nrm), "f"(v.w * nrm)
                 : "memory");
}

// Self-loop contribution + relu: y = relu(acc + h * dinv^2), float4 lanes.
__global__ void finalize_conv(const float4* __restrict__ acc, const float4* __restrict__ h,
                              const float* __restrict__ dinv, float4* __restrict__ y, int n4)
{
    int i = blockIdx.x * blockDim.x + threadIdx.x;
    if (i >= n4) return;
    int node = i >> 5;  // /(HH/4)
    float di = dinv[node];
    float w = di * di;
    float4 a = acc[i], hh = h[i];
    float4 r;
    r.x = fmaxf(fmaf(hh.x, w, a.x), 0.f);
    r.y = fmaxf(fmaf(hh.y, w, a.y), 0.f);
    r.z = fmaxf(fmaf(hh.z, w, a.z), 0.f);
    r.w = fmaxf(fmaf(hh.w, w, a.w), 0.f);
    y[i] = r;
}

// ---------------------------------------------------------------------------
// log_softmax over C=64 classes; 1 warp per row, 2 classes per lane.
// ---------------------------------------------------------------------------
__global__ void log_softmax_k(const float* __restrict__ logits, float* __restrict__ out, int N)
{
    int row = blockIdx.x * blockDim.y + threadIdx.y;
    if (row >= N) return;
    int lane = threadIdx.x;
    const float* lr = logits + (size_t)row * CC;
    float v0 = lr[lane], v1 = lr[lane + 32];
    float m = fmaxf(v0, v1);
#pragma unroll
    for (int o = 16; o; o >>= 1) m = fmaxf(m, __shfl_xor_sync(0xffffffffu, m, o));
    float s = expf(v0 - m) + expf(v1 - m);
#pragma unroll
    for (int o = 16; o; o >>= 1) s += __shfl_xor_sync(0xffffffffu, s, o);
    float ls = m + logf(s);
    float* orow = out + (size_t)row * CC;
    orow[lane] = v0 - ls;
    orow[lane + 32] = v1 - ls;
}

// ---------------------------------------------------------------------------
// Launch
// ---------------------------------------------------------------------------
extern "C" void kernel_launch(void* const* d_in, const int* in_sizes, int n_in,
                              void* d_out, int out_size)
{
    const float* x     = (const float*)d_in[0];
    const int*   ei    = (const int*)d_in[1];
    const float* W0    = (const float*)d_in[2];
    const float* b0    = (const float*)d_in[3];
    const float* W1    = (const float*)d_in[4];
    const float* b1    = (const float*)d_in[5];
    const float* W2    = (const float*)d_in[6];
    const float* b2    = (const float*)d_in[7];
    const float* fc1_w = (const float*)d_in[8];
    const float* fc1_b = (const float*)d_in[9];
    const float* fc2_w = (const float*)d_in[10];
    const float* fc2_b = (const float*)d_in[11];
    const float* fc3_w = (const float*)d_in[12];
    const float* fc3_b = (const float*)d_in[13];

    const int N = in_sizes[0] / FIN;   // 100000
    const int E = in_sizes[1] / 2;     // 1600000
    const int* src = ei;
    const int* dst = ei + E;

    float *h_, *acc_, *y_, *dinv_, *norm_;
    cudaGetSymbolAddress((void**)&h_,    g_h);
    cudaGetSymbolAddress((void**)&acc_,  g_acc);
    cudaGetSymbolAddress((void**)&y_,    g_y);
    cudaGetSymbolAddress((void**)&dinv_, g_dinv);
    cudaGetSymbolAddress((void**)&norm_, g_norm);

    const int T = 256;
    dim3 gemm_grid((N + BM - 1) / BM, HH / BN);     // 782 x 2
    dim3 gemm_grid_c((N + BM - 1) / BM, CC / BN);   // 782 x 1

    // ---- graph normalization ----
    cudaMemsetAsync(dinv_, 0, (size_t)N * sizeof(float));
    count_deg<<<(E + T - 1) / T, T>>>(dst, dinv_, E);
    fin_deg<<<(N + T - 1) / T, T>>>(dinv_, N);
    comp_norm<<<(E + T - 1) / T, T>>>(src, dst, dinv_, norm_, E);

    const int scatter_blocks = (int)(((size_t)E * 32 + T - 1) / T);
    const int nh = N * HH;
    const int nh4 = nh / 4;

    // ---- conv0: x[N,512] @ W0 -> scatter -> relu -> y_ ----
    sgemm_bias<<<gemm_grid, T>>>(x, W0, b0, h_, N, FIN, HH, 0);
    cudaMemsetAsync(acc_, 0, (size_t)nh * sizeof(float));
    scatter_edges<<<scatter_blocks, T>>>(h_, src, dst, norm_, acc_, E);
    finalize_conv<<<(nh4 + T - 1) / T, T>>>((const float4*)acc_, (const float4*)h_,
                                            dinv_, (float4*)y_, nh4);

    // ---- conv1 ----
    sgemm_bias<<<gemm_grid, T>>>(y_, W1, b1, h_, N, HH, HH, 0);
    cudaMemsetAsync(acc_, 0, (size_t)nh * sizeof(float));
    scatter_edges<<<scatter_blocks, T>>>(h_, src, dst, norm_, acc_, E);
    finalize_conv<<<(nh4 + T - 1) / T, T>>>((const float4*)acc_, (const float4*)h_,
                                            dinv_, (float4*)y_, nh4);

    // ---- conv2 ----
    sgemm_bias<<<gemm_grid, T>>>(y_, W2, b2, h_, N, HH, HH, 0);
    cudaMemsetAsync(acc_, 0, (size_t)nh * sizeof(float));
    scatter_edges<<<scatter_blocks, T>>>(h_, src, dst, norm_, acc_, E);
    finalize_conv<<<(nh4 + T - 1) / T, T>>>((const float4*)acc_, (const float4*)h_,
                                            dinv_, (float4*)y_, nh4);

    // ---- MLP ----
    sgemm_bias<<<gemm_grid, T>>>(y_, fc1_w, fc1_b, h_, N, HH, HH, 1);
    sgemm_bias<<<gemm_grid, T>>>(h_, fc2_w, fc2_b, y_, N, HH, HH, 1);
    sgemm_bias<<<gemm_grid_c, T>>>(y_, fc3_w, fc3_b, acc_, N, HH, CC, 0);

    // ---- log_softmax ----
    dim3 ls_block(32, 8);
    log_softmax_k<<<(N + 7) / 8, ls_block>>>(acc_, (float*)d_out, N);
}